// round 6
// baseline (speedup 1.0000x reference)
#include <cuda_runtime.h>
#include <cuda_fp16.h>
#include <cstdint>

#define BQ     2
#define NSEQ   4096
#define DMODEL 512
#define NH     8
#define HDIM   64
#define WSTR   72   // proj smem stride (halves): 144B rows, conflict-free frag loads
#define KSTR   72   // attn K-tile stride (halves)

// Scratch (allocation-free __device__ globals), fp16.
__device__ __half g_x [BQ*NSEQ*DMODEL];   // x  as fp16 (8 MB)
__device__ __half g_wq[DMODEL*DMODEL];    // Wq as fp16 (0.5 MB)
__device__ __half g_wk[DMODEL*DMODEL];    // Wk as fp16 (0.5 MB)
__device__ __half g_q [BQ*NH*NSEQ*HDIM];  // [b,h,n,hd], pre-scaled by D^-0.5*log2e
__device__ __half g_k [BQ*NH*NSEQ*HDIM];  // [b,h,n,hd]  (v == k per reference bug)

// ---------------------------------------------------------------------------
// helpers (base sm_103 PTX only)
// ---------------------------------------------------------------------------
__device__ __forceinline__ uint32_t smem_u32(const void* p) {
    uint32_t a;
    asm("{ .reg .u64 t; cvta.to.shared.u64 t, %1; cvt.u32.u64 %0, t; }" : "=r"(a) : "l"(p));
    return a;
}
__device__ __forceinline__ float ex2(float x) {
    float r; asm("ex2.approx.ftz.f32 %0, %1;" : "=f"(r) : "f"(x)); return r;
}
// fp16: D += A(16x16) * B(16x8), fp32 accum
__device__ __forceinline__ void mma16(float* c, const uint32_t* a, uint32_t b0, uint32_t b1) {
    asm volatile("mma.sync.aligned.m16n8k16.row.col.f32.f16.f16.f32 "
        "{%0,%1,%2,%3}, {%4,%5,%6,%7}, {%8,%9}, {%0,%1,%2,%3};"
        : "+f"(c[0]), "+f"(c[1]), "+f"(c[2]), "+f"(c[3])
        : "r"(a[0]), "r"(a[1]), "r"(a[2]), "r"(a[3]), "r"(b0), "r"(b1));
}
__device__ __forceinline__ void ldsm4(uint32_t* r, uint32_t addr) {
    asm volatile("ldmatrix.sync.aligned.m8n8.x4.shared.b16 {%0,%1,%2,%3}, [%4];"
        : "=r"(r[0]), "=r"(r[1]), "=r"(r[2]), "=r"(r[3]) : "r"(addr));
}
__device__ __forceinline__ void ldsm4t(uint32_t* r, uint32_t addr) {
    asm volatile("ldmatrix.sync.aligned.m8n8.x4.trans.shared.b16 {%0,%1,%2,%3}, [%4];"
        : "=r"(r[0]), "=r"(r[1]), "=r"(r[2]), "=r"(r[3]) : "r"(addr));
}
__device__ __forceinline__ void cpa16(uint32_t dst, const void* src) {
    asm volatile("cp.async.cg.shared.global [%0], [%1], 16;" :: "r"(dst), "l"(src) : "memory");
}
#define CP_COMMIT() asm volatile("cp.async.commit_group;" ::: "memory")
#define CP_WAIT0()  asm volatile("cp.async.wait_group 0;" ::: "memory")
#define CP_WAIT1()  asm volatile("cp.async.wait_group 1;" ::: "memory")

__device__ __forceinline__ uint32_t pack_h2(float lo, float hi) {
    __half2 h = __floats2half2_rn(lo, hi);
    return *(uint32_t*)&h;
}

// ---------------------------------------------------------------------------
// fp32 -> fp16 pre-pass (vectorized grid-stride)
// ---------------------------------------------------------------------------
__global__ void f2h_kernel(const float* __restrict__ in, __half* __restrict__ out, int n4)
{
    int i = blockIdx.x * blockDim.x + threadIdx.x;
    const int stride = gridDim.x * blockDim.x;
    for (; i < n4; i += stride) {
        float4 v = ((const float4*)in)[i];
        ((__half2*)out)[2 * i]     = __floats2half2_rn(v.x, v.y);
        ((__half2*)out)[2 * i + 1] = __floats2half2_rn(v.z, v.w);
    }
}

// ---------------------------------------------------------------------------
// Fused Q+K projection, fp16 mma, cp.async double-buffered over the K dim.
// CTA: 256 thr / 8 warps; M=128 rows, one head (64 cols) for BOTH Wq and Wk.
// smem: Xs[2][128][WSTR] + Ws[2][128][WSTR] halves = 73728 B
//       (Ws rows 0-63 = Wq head rows, 64-127 = Wk head rows).
// ---------------------------------------------------------------------------
__global__ __launch_bounds__(256, 2) void proj_fused(float qscale,
                                                     const float* __restrict__ bq,
                                                     const float* __restrict__ bk)
{
    extern __shared__ __half smh[];
    const uint32_t xs0 = smem_u32(smh);
    const uint32_t xs1 = xs0 + 128 * WSTR * 2;
    const uint32_t ws0 = xs1 + 128 * WSTR * 2;
    const uint32_t ws1 = ws0 + 128 * WSTR * 2;

    const int tid  = threadIdx.x;
    const int w    = tid >> 5;
    const int lane = tid & 31;
    const int g    = lane >> 2;
    const int tg   = lane & 3;
    const int h  = blockIdx.x;
    const int m0 = blockIdx.y * 128;
    const int e0 = h * 64;

    // per-thread cp.async chunk coords (8 chunks: 4 X + 4 W)
    // X tile: 128 rows x 64 halves (8 chunks/row); W tile: same, rows = 2x64.
    auto stage = [&](uint32_t xb, uint32_t wb, int kc) {
        const int k0 = kc * 64;
        #pragma unroll
        for (int p = 0; p < 4; p++) {
            int f = tid + p * 256;            // 0..1023
            int row = f >> 3, c = f & 7;
            cpa16(xb + (uint32_t)(row * WSTR + c * 8) * 2,
                  g_x + (size_t)(m0 + row) * DMODEL + k0 + c * 8);
        }
        #pragma unroll
        for (int p = 0; p < 4; p++) {
            int f = tid + p * 256;
            int row = f >> 3, c = f & 7;
            const __half* src = (row < 64)
                ? g_wq + (size_t)(e0 + row) * DMODEL + k0 + c * 8
                : g_wk + (size_t)(e0 + row - 64) * DMODEL + k0 + c * 8;
            cpa16(wb + (uint32_t)(row * WSTR + c * 8) * 2, src);
        }
        CP_COMMIT();
    };

    stage(xs0, ws0, 0);

    float acc[16][4] = {};

    for (int kc = 0; kc < DMODEL / 64; kc++) {
        __syncthreads();
        if (kc + 1 < DMODEL / 64) {
            stage((kc + 1) & 1 ? xs1 : xs0, (kc + 1) & 1 ? ws1 : ws0, kc + 1);
            CP_WAIT1();
        } else {
            CP_WAIT0();
        }
        __syncthreads();

        const uint32_t xb = (kc & 1) ? xs1 : xs0;
        const uint32_t wb = (kc & 1) ? ws1 : ws0;

        #pragma unroll
        for (int kb = 0; kb < 4; kb++) {      // k16 blocks
            uint32_t a[4];
            const uint32_t abase = xb + (uint32_t)((w * 16 + g) * WSTR + kb * 16 + 2 * tg) * 2;
            asm volatile("ld.shared.b32 %0, [%1];"       : "=r"(a[0]) : "r"(abase));
            asm volatile("ld.shared.b32 %0, [%1 + %2];"  : "=r"(a[1]) : "r"(abase), "n"(8 * WSTR * 2));
            asm volatile("ld.shared.b32 %0, [%1 + 16];"  : "=r"(a[2]) : "r"(abase));
            asm volatile("ld.shared.b32 %0, [%1 + %2];"  : "=r"(a[3]) : "r"(abase), "n"(8 * WSTR * 2 + 16));
            #pragma unroll
            for (int nb = 0; nb < 16; nb++) {
                uint32_t b0, b1;
                const uint32_t bbase = wb + (uint32_t)((nb * 8 + g) * WSTR + kb * 16 + 2 * tg) * 2;
                asm volatile("ld.shared.b32 %0, [%1];"      : "=r"(b0) : "r"(bbase));
                asm volatile("ld.shared.b32 %0, [%1 + 16];" : "=r"(b1) : "r"(bbase));
                mma16(acc[nb], a, b0, b1);
            }
        }
    }

    // epilogue: bias (+scale for Q), pack fp16, store [b,h,n,hd]
    const int b_ = m0 / NSEQ;
    const int n0 = m0 % NSEQ;
    const size_t obase = ((size_t)(b_ * NH + h) * NSEQ + n0 + w * 16 + g) * HDIM;
    #pragma unroll
    for (int nb = 0; nb < 8; nb++) {
        const int e = nb * 8 + 2 * tg;
        // Q (scaled)
        {
            const float bv0 = bq[e0 + e], bv1 = bq[e0 + e + 1];
            uint32_t u0 = pack_h2((acc[nb][0] + bv0) * qscale, (acc[nb][1] + bv1) * qscale);
            uint32_t u1 = pack_h2((acc[nb][2] + bv0) * qscale, (acc[nb][3] + bv1) * qscale);
            *(uint32_t*)&g_q[obase + e]            = u0;
            *(uint32_t*)&g_q[obase + 8 * HDIM + e] = u1;
        }
        // K
        {
            const float bv0 = bk[e0 + e], bv1 = bk[e0 + e + 1];
            uint32_t u0 = pack_h2(acc[nb + 8][0] + bv0, acc[nb + 8][1] + bv1);
            uint32_t u1 = pack_h2(acc[nb + 8][2] + bv0, acc[nb + 8][3] + bv1);
            *(uint32_t*)&g_k[obase + e]            = u0;
            *(uint32_t*)&g_k[obase + 8 * HDIM + e] = u1;
        }
    }
}

// ---------------------------------------------------------------------------
// Flash attention, fp16 mma.sync m16n8k16 (unchanged from R5 — near roofline).
// ---------------------------------------------------------------------------
__global__ __launch_bounds__(256, 2) void attn_mma(float* __restrict__ out)
{
    extern __shared__ __half smh[];
    const uint32_t ks0 = smem_u32(smh);
    const uint32_t ks1 = ks0 + 64 * KSTR * 2;

    const int tid  = threadIdx.x;
    const int w    = tid >> 5;
    const int lane = tid & 31;
    const int g    = lane >> 2;
    const int tg   = lane & 3;
    const int bh = blockIdx.y;
    const int q0 = blockIdx.x * 128;

    const __half* kbase = g_k + (size_t)bh * NSEQ * HDIM;

    const int lrow = (lane & 7) + ((lane >> 3) & 1) * 8;
    const int lcol = ((lane >> 4) & 1) * 8;
    const uint32_t lbase = (uint32_t)(lrow * KSTR + lcol) * 2;

    uint32_t qf[4][4];
    {
        const __half* qr = g_q + ((size_t)bh * NSEQ + q0 + w * 16 + g) * HDIM;
        #pragma unroll
        for (int kb = 0; kb < 4; kb++) {
            const int c = kb * 16 + 2 * tg;
            qf[kb][0] = *(const uint32_t*)&qr[c];
            qf[kb][1] = *(const uint32_t*)&qr[c + 8 * HDIM];
            qf[kb][2] = *(const uint32_t*)&qr[c + 8];
            qf[kb][3] = *(const uint32_t*)&qr[c + 8 * HDIM + 8];
        }
    }

    {
        #pragma unroll
        for (int p = 0; p < 2; p++) {
            int f = tid + p * 256;
            int row = f >> 3, c = f & 7;
            cpa16(ks0 + (uint32_t)(row * KSTR + c * 8) * 2, kbase + row * HDIM + c * 8);
        }
        CP_COMMIT();
    }

    float o[8][4] = {};
    float li0 = 0.f, li1 = 0.f;

    for (int t = 0; t < NSEQ / 64; t++) {
        __syncthreads();
        if (t + 1 < NSEQ / 64) {
            const __half* kt = kbase + (size_t)(t + 1) * 64 * HDIM;
            const uint32_t dstb = ((t + 1) & 1) ? ks1 : ks0;
            #pragma unroll
            for (int p = 0; p < 2; p++) {
                int f = tid + p * 256;
                int row = f >> 3, c = f & 7;
                cpa16(dstb + (uint32_t)(row * KSTR + c * 8) * 2, kt + row * HDIM + c * 8);
            }
            CP_COMMIT();
            CP_WAIT1();
        } else {
            CP_WAIT0();
        }
        __syncthreads();

        const uint32_t K = (t & 1) ? ks1 : ks0;

        #pragma unroll
        for (int j = 0; j < 4; j++) {
            float s0[4] = {}, s1[4] = {};
            #pragma unroll
            for (int kb = 0; kb < 4; kb++) {
                uint32_t r[4];
                ldsm4(r, K + lbase + (uint32_t)(j * 16 * KSTR + kb * 16) * 2);
                mma16(s0, qf[kb], r[0], r[2]);
                mma16(s1, qf[kb], r[1], r[3]);
            }
            float p00 = ex2(s0[0]), p01 = ex2(s0[1]);
            float p02 = ex2(s0[2]), p03 = ex2(s0[3]);
            float p10 = ex2(s1[0]), p11 = ex2(s1[1]);
            float p12 = ex2(s1[2]), p13 = ex2(s1[3]);
            li0 += (p00 + p01) + (p10 + p11);
            li1 += (p02 + p03) + (p12 + p13);
            uint32_t a[4];
            a[0] = pack_h2(p00, p01);
            a[1] = pack_h2(p02, p03);
            a[2] = pack_h2(p10, p11);
            a[3] = pack_h2(p12, p13);
            #pragma unroll
            for (int p = 0; p < 4; p++) {
                uint32_t v[4];
                ldsm4t(v, K + lbase + (uint32_t)(j * 16 * KSTR + p * 16) * 2);
                mma16(o[2 * p],     a, v[0], v[1]);
                mma16(o[2 * p + 1], a, v[2], v[3]);
            }
        }
    }

    li0 += __shfl_xor_sync(0xffffffffu, li0, 1);
    li0 += __shfl_xor_sync(0xffffffffu, li0, 2);
    li1 += __shfl_xor_sync(0xffffffffu, li1, 1);
    li1 += __shfl_xor_sync(0xffffffffu, li1, 2);
    const float inv0 = 1.0f / li0;
    const float inv1 = 1.0f / li1;

    const int b_ = bh >> 3;
    const int h  = bh & 7;
    const int row0 = q0 + w * 16 + g;
    #pragma unroll
    for (int nb = 0; nb < 8; nb++) {
        const int col = h * HDIM + nb * 8 + 2 * tg;
        *(float2*)&out[((size_t)b_ * NSEQ + row0) * DMODEL + col] =
            make_float2(o[nb][0] * inv0, o[nb][1] * inv0);
        *(float2*)&out[((size_t)b_ * NSEQ + row0 + 8) * DMODEL + col] =
            make_float2(o[nb][2] * inv1, o[nb][3] * inv1);
    }
}

extern "C" void kernel_launch(void* const* d_in, const int* in_sizes, int n_in,
                              void* d_out, int out_size)
{
    const float* x  = (const float*)d_in[0];
    const float* Wq = (const float*)d_in[1];
    const float* bq = (const float*)d_in[2];
    const float* Wk = (const float*)d_in[3];
    const float* bk = (const float*)d_in[4];
    float* out = (float*)d_out;

    const int psmem = 4 * 128 * WSTR * 2;    // 73728 B
    const int asmem = 2 * 64 * KSTR * 2;     // 18432 B
    cudaFuncSetAttribute(proj_fused, cudaFuncAttributeMaxDynamicSharedMemorySize, psmem);
    cudaFuncSetAttribute(attn_mma,  cudaFuncAttributeMaxDynamicSharedMemorySize, asmem);

    __half *gx, *gwq, *gwk;
    cudaGetSymbolAddress((void**)&gx,  g_x);
    cudaGetSymbolAddress((void**)&gwq, g_wq);
    cudaGetSymbolAddress((void**)&gwk, g_wk);

    const float qscale = 0.044194173824159216f * 1.4426950408889634f; // D^-1/2 * log2e

    f2h_kernel<<<1024, 256>>>(x,  gx,  BQ * NSEQ * DMODEL / 4);
    f2h_kernel<<<128,  256>>>(Wq, gwq, DMODEL * DMODEL / 4);
    f2h_kernel<<<128,  256>>>(Wk, gwk, DMODEL * DMODEL / 4);
    proj_fused<<<dim3(NH, (BQ * NSEQ) / 128), 256, psmem>>>(qscale, bq, bk);
    attn_mma<<<dim3(NSEQ / 128, BQ * NH), 256, asmem>>>(out);
}

// round 7
// speedup vs baseline: 1.4690x; 1.4690x over previous
#include <cuda_runtime.h>
#include <cuda_fp16.h>
#include <cstdint>

#define BQ     2
#define NSEQ   4096
#define DMODEL 512
#define NH     8
#define HDIM   64
#define WSTR   72   // proj smem stride (halves): 144B rows, ldmatrix conflict-free
#define KSTR   72   // attn K-tile stride (halves)

// Scratch (allocation-free __device__ globals), fp16, 8 MB each.
__device__ __half g_q[BQ*NH*NSEQ*HDIM];   // [b,h,n,hd], pre-scaled by D^-0.5*log2e
__device__ __half g_k[BQ*NH*NSEQ*HDIM];   // [b,h,n,hd]  (v == k per reference bug)

// ---------------------------------------------------------------------------
// helpers (base sm_103 PTX only)
// ---------------------------------------------------------------------------
__device__ __forceinline__ uint32_t smem_u32(const void* p) {
    uint32_t a;
    asm("{ .reg .u64 t; cvta.to.shared.u64 t, %1; cvt.u32.u64 %0, t; }" : "=r"(a) : "l"(p));
    return a;
}
__device__ __forceinline__ float ex2(float x) {
    float r; asm("ex2.approx.ftz.f32 %0, %1;" : "=f"(r) : "f"(x)); return r;
}
// fp16: D += A(16x16) * B(16x8), fp32 accum
__device__ __forceinline__ void mma16(float* c, const uint32_t* a, uint32_t b0, uint32_t b1) {
    asm volatile("mma.sync.aligned.m16n8k16.row.col.f32.f16.f16.f32 "
        "{%0,%1,%2,%3}, {%4,%5,%6,%7}, {%8,%9}, {%0,%1,%2,%3};"
        : "+f"(c[0]), "+f"(c[1]), "+f"(c[2]), "+f"(c[3])
        : "r"(a[0]), "r"(a[1]), "r"(a[2]), "r"(a[3]), "r"(b0), "r"(b1));
}
__device__ __forceinline__ void ldsm4(uint32_t* r, uint32_t addr) {
    asm volatile("ldmatrix.sync.aligned.m8n8.x4.shared.b16 {%0,%1,%2,%3}, [%4];"
        : "=r"(r[0]), "=r"(r[1]), "=r"(r[2]), "=r"(r[3]) : "r"(addr));
}
__device__ __forceinline__ void ldsm4t(uint32_t* r, uint32_t addr) {
    asm volatile("ldmatrix.sync.aligned.m8n8.x4.trans.shared.b16 {%0,%1,%2,%3}, [%4];"
        : "=r"(r[0]), "=r"(r[1]), "=r"(r[2]), "=r"(r[3]) : "r"(addr));
}
__device__ __forceinline__ void cpa16(uint32_t dst, const void* src) {
    asm volatile("cp.async.cg.shared.global [%0], [%1], 16;" :: "r"(dst), "l"(src) : "memory");
}
#define CP_COMMIT() asm volatile("cp.async.commit_group;" ::: "memory")
#define CP_WAIT0()  asm volatile("cp.async.wait_group 0;" ::: "memory")
#define CP_WAIT1()  asm volatile("cp.async.wait_group 1;" ::: "memory")

__device__ __forceinline__ uint32_t pack_h2(float lo, float hi) {
    __half2 h = __floats2half2_rn(lo, hi);
    return *(uint32_t*)&h;
}

// ---------------------------------------------------------------------------
// Projection, fp16 mma m16n8k16 + ldmatrix + register-prefetch pipeline.
// Y[m,e] = X[m,:]·W[e,:] + bias[e], times oscale, stored fp16 to dst [b,h,n,hd].
// CTA: 256 thr / 8 warps; M=128 rows, N=64 (one head), K loop 8 x 64.
// smem: Xh[128][WSTR] + Wh[64][WSTR] halves = 27648 B.
// ---------------------------------------------------------------------------
__global__ __launch_bounds__(256, 2) void proj_mma(const float* __restrict__ X,
                                                   const float* __restrict__ W,
                                                   const float* __restrict__ bias,
                                                   __half* __restrict__ dst,
                                                   float oscale)
{
    extern __shared__ __half smh[];
    __half* Xh = smh;                 // [128][WSTR]
    __half* Wh = smh + 128 * WSTR;    // [64][WSTR]
    const uint32_t xA = smem_u32(Xh);
    const uint32_t wA = smem_u32(Wh);

    const int tid  = threadIdx.x;
    const int w    = tid >> 5;
    const int lane = tid & 31;
    const int g    = lane >> 2;
    const int tg   = lane & 3;
    const int h  = blockIdx.x;
    const int m0 = blockIdx.y * 128;
    const int e0 = h * 64;

    // ldmatrix per-thread source coords (standard x4 mapping)
    const int lrow = (lane & 7) + ((lane >> 3) & 1) * 8;
    const int lcol = ((lane >> 4) & 1) * 8;

    // per-thread fill coords: X 8 float4 chunks, W 4 chunks
    const int xrow[2] = { tid >> 4, 0 };  // pattern: f = tid + p*256
    (void)xrow;

    float4 xr[8], wr[4];
    auto ldg_tile = [&](int kc) {
        const int k0 = kc * 64;
        #pragma unroll
        for (int p = 0; p < 8; p++) {
            int f = tid + p * 256;                 // 0..2047
            int row = f >> 4, c4 = (f & 15) * 4;
            xr[p] = *(const float4*)&X[(size_t)(m0 + row) * DMODEL + k0 + c4];
        }
        #pragma unroll
        for (int p = 0; p < 4; p++) {
            int f = tid + p * 256;                 // 0..1023
            int row = f >> 4, c4 = (f & 15) * 4;
            wr[p] = *(const float4*)&W[(size_t)(e0 + row) * DMODEL + k0 + c4];
        }
    };
    auto sts_tile = [&]() {
        #pragma unroll
        for (int p = 0; p < 8; p++) {
            int f = tid + p * 256;
            int row = f >> 4, c4 = (f & 15) * 4;
            *(uint2*)&Xh[row * WSTR + c4] =
                make_uint2(pack_h2(xr[p].x, xr[p].y), pack_h2(xr[p].z, xr[p].w));
        }
        #pragma unroll
        for (int p = 0; p < 4; p++) {
            int f = tid + p * 256;
            int row = f >> 4, c4 = (f & 15) * 4;
            *(uint2*)&Wh[row * WSTR + c4] =
                make_uint2(pack_h2(wr[p].x, wr[p].y), pack_h2(wr[p].z, wr[p].w));
        }
    };

    ldg_tile(0);
    float acc[8][4] = {};

    for (int kc = 0; kc < DMODEL / 64; kc++) {
        __syncthreads();            // previous MMA phase done reading smem
        sts_tile();
        __syncthreads();
        if (kc + 1 < DMODEL / 64) ldg_tile(kc + 1);   // hides under MMA below

        #pragma unroll
        for (int kb = 0; kb < 4; kb++) {
            uint32_t a[4];
            ldsm4(a, xA + (uint32_t)((w * 16 + lrow) * WSTR + kb * 16 + lcol) * 2);
            #pragma unroll
            for (int wb = 0; wb < 4; wb++) {
                uint32_t r[4];
                ldsm4(r, wA + (uint32_t)((wb * 16 + lrow) * WSTR + kb * 16 + lcol) * 2);
                mma16(acc[2 * wb],     a, r[0], r[2]);   // e rows wb*16 + 0..7
                mma16(acc[2 * wb + 1], a, r[1], r[3]);   // e rows wb*16 + 8..15
            }
        }
    }

    // epilogue: bias, scale, pack fp16, store [b,h,n,hd]
    const int b_ = m0 / NSEQ;
    const int n0 = m0 % NSEQ;
    const size_t obase = ((size_t)(b_ * NH + h) * NSEQ + n0 + w * 16 + g) * HDIM;
    #pragma unroll
    for (int nb = 0; nb < 8; nb++) {
        const int e = nb * 8 + 2 * tg;
        const float bv0 = bias[e0 + e], bv1 = bias[e0 + e + 1];
        uint32_t u0 = pack_h2((acc[nb][0] + bv0) * oscale, (acc[nb][1] + bv1) * oscale);
        uint32_t u1 = pack_h2((acc[nb][2] + bv0) * oscale, (acc[nb][3] + bv1) * oscale);
        *(uint32_t*)&dst[obase + e]            = u0;
        *(uint32_t*)&dst[obase + 8 * HDIM + e] = u1;
    }
}

// ---------------------------------------------------------------------------
// Flash attention, fp16 mma.sync m16n8k16 (identical to R5 — proven 161.6us).
// ---------------------------------------------------------------------------
__global__ __launch_bounds__(256, 2) void attn_mma(float* __restrict__ out)
{
    extern __shared__ __half smh[];
    const uint32_t ks0 = smem_u32(smh);
    const uint32_t ks1 = ks0 + 64 * KSTR * 2;

    const int tid  = threadIdx.x;
    const int w    = tid >> 5;
    const int lane = tid & 31;
    const int g    = lane >> 2;
    const int tg   = lane & 3;
    const int bh = blockIdx.y;
    const int q0 = blockIdx.x * 128;

    const __half* kbase = g_k + (size_t)bh * NSEQ * HDIM;

    const int lrow = (lane & 7) + ((lane >> 3) & 1) * 8;
    const int lcol = ((lane >> 4) & 1) * 8;
    const uint32_t lbase = (uint32_t)(lrow * KSTR + lcol) * 2;

    uint32_t qf[4][4];
    {
        const __half* qr = g_q + ((size_t)bh * NSEQ + q0 + w * 16 + g) * HDIM;
        #pragma unroll
        for (int kb = 0; kb < 4; kb++) {
            const int c = kb * 16 + 2 * tg;
            qf[kb][0] = *(const uint32_t*)&qr[c];
            qf[kb][1] = *(const uint32_t*)&qr[c + 8 * HDIM];
            qf[kb][2] = *(const uint32_t*)&qr[c + 8];
            qf[kb][3] = *(const uint32_t*)&qr[c + 8 * HDIM + 8];
        }
    }

    {
        #pragma unroll
        for (int p = 0; p < 2; p++) {
            int f = tid + p * 256;
            int row = f >> 3, c = f & 7;
            cpa16(ks0 + (uint32_t)(row * KSTR + c * 8) * 2, kbase + row * HDIM + c * 8);
        }
        CP_COMMIT();
    }

    float o[8][4] = {};
    float li0 = 0.f, li1 = 0.f;

    for (int t = 0; t < NSEQ / 64; t++) {
        __syncthreads();
        if (t + 1 < NSEQ / 64) {
            const __half* kt = kbase + (size_t)(t + 1) * 64 * HDIM;
            const uint32_t dstb = ((t + 1) & 1) ? ks1 : ks0;
            #pragma unroll
            for (int p = 0; p < 2; p++) {
                int f = tid + p * 256;
                int row = f >> 3, c = f & 7;
                cpa16(dstb + (uint32_t)(row * KSTR + c * 8) * 2, kt + row * HDIM + c * 8);
            }
            CP_COMMIT();
            CP_WAIT1();
        } else {
            CP_WAIT0();
        }
        __syncthreads();

        const uint32_t K = (t & 1) ? ks1 : ks0;

        #pragma unroll
        for (int j = 0; j < 4; j++) {
            float s0[4] = {}, s1[4] = {};
            #pragma unroll
            for (int kb = 0; kb < 4; kb++) {
                uint32_t r[4];
                ldsm4(r, K + lbase + (uint32_t)(j * 16 * KSTR + kb * 16) * 2);
                mma16(s0, qf[kb], r[0], r[2]);
                mma16(s1, qf[kb], r[1], r[3]);
            }
            float p00 = ex2(s0[0]), p01 = ex2(s0[1]);
            float p02 = ex2(s0[2]), p03 = ex2(s0[3]);
            float p10 = ex2(s1[0]), p11 = ex2(s1[1]);
            float p12 = ex2(s1[2]), p13 = ex2(s1[3]);
            li0 += (p00 + p01) + (p10 + p11);
            li1 += (p02 + p03) + (p12 + p13);
            uint32_t a[4];
            a[0] = pack_h2(p00, p01);
            a[1] = pack_h2(p02, p03);
            a[2] = pack_h2(p10, p11);
            a[3] = pack_h2(p12, p13);
            #pragma unroll
            for (int p = 0; p < 4; p++) {
                uint32_t v[4];
                ldsm4t(v, K + lbase + (uint32_t)(j * 16 * KSTR + p * 16) * 2);
                mma16(o[2 * p],     a, v[0], v[1]);
                mma16(o[2 * p + 1], a, v[2], v[3]);
            }
        }
    }

    li0 += __shfl_xor_sync(0xffffffffu, li0, 1);
    li0 += __shfl_xor_sync(0xffffffffu, li0, 2);
    li1 += __shfl_xor_sync(0xffffffffu, li1, 1);
    li1 += __shfl_xor_sync(0xffffffffu, li1, 2);
    const float inv0 = 1.0f / li0;
    const float inv1 = 1.0f / li1;

    const int b_ = bh >> 3;
    const int h  = bh & 7;
    const int row0 = q0 + w * 16 + g;
    #pragma unroll
    for (int nb = 0; nb < 8; nb++) {
        const int col = h * HDIM + nb * 8 + 2 * tg;
        *(float2*)&out[((size_t)b_ * NSEQ + row0) * DMODEL + col] =
            make_float2(o[nb][0] * inv0, o[nb][1] * inv0);
        *(float2*)&out[((size_t)b_ * NSEQ + row0 + 8) * DMODEL + col] =
            make_float2(o[nb][2] * inv1, o[nb][3] * inv1);
    }
}

extern "C" void kernel_launch(void* const* d_in, const int* in_sizes, int n_in,
                              void* d_out, int out_size)
{
    const float* x  = (const float*)d_in[0];
    const float* Wq = (const float*)d_in[1];
    const float* bq = (const float*)d_in[2];
    const float* Wk = (const float*)d_in[3];
    const float* bk = (const float*)d_in[4];
    float* out = (float*)d_out;

    const int psmem = 192 * WSTR * 2;        // 27648 B
    const int asmem = 2 * 64 * KSTR * 2;     // 18432 B
    cudaFuncSetAttribute(proj_mma, cudaFuncAttributeMaxDynamicSharedMemorySize, psmem);
    cudaFuncSetAttribute(attn_mma, cudaFuncAttributeMaxDynamicSharedMemorySize, asmem);

    __half* gq; cudaGetSymbolAddress((void**)&gq, g_q);
    __half* gk; cudaGetSymbolAddress((void**)&gk, g_k);

    const float qscale = 0.044194173824159216f * 1.4426950408889634f; // D^-1/2 * log2e

    dim3 pgrid(NH, (BQ * NSEQ) / 128);           // (8, 64)
    proj_mma<<<pgrid, 256, psmem>>>(x, Wq, bq, gq, qscale);
    proj_mma<<<pgrid, 256, psmem>>>(x, Wk, bk, gk, 1.0f);
    attn_mma<<<dim3(NSEQ / 128, BQ * NH), 256, asmem>>>(out);
}